// round 1
// baseline (speedup 1.0000x reference)
#include <cuda_runtime.h>
#include <math.h>

#define BB 16
#define HH 384
#define WW 384
#define NPIX (BB * HH * WW)

// Scratch: squared horizontal distance per pixel (allowed: __device__ global)
__device__ float g_g2[NPIX];
__device__ float g_accum;

// ---------------------------------------------------------------------------
// Kernel 1: per-row 1D distance to nearest foreground pixel (exact).
// One block per (b, row), WW threads. Row staged in shared memory.
// Early-exit outward search: with Bernoulli(0.5) targets this terminates in
// ~1-2 iterations per pixel. If no fg in the row, g = BIG = H + W = 768
// (matches reference's clip(min(d_left, d_right), 0, BIG)).
// Also zeroes the global accumulator (thread 0 of block 0).
// ---------------------------------------------------------------------------
__global__ void row_dist_kernel(const int* __restrict__ targets) {
    __shared__ int srow[WW];
    const int rowIdx = blockIdx.x;                  // 0 .. B*H-1
    const int j = threadIdx.x;
    const int* trow = targets + (size_t)rowIdx * WW;
    srow[j] = trow[j];
    if (rowIdx == 0 && j == 0) g_accum = 0.0f;
    __syncthreads();

    float g;
    if (srow[j] != 0) {
        g = 0.0f;
    } else {
        const int rmax = max(j, WW - 1 - j);
        int r = 1;
        int found = 0;
        for (; r <= rmax; ++r) {
            int hit = 0;
            if (j - r >= 0 && srow[j - r]) hit = 1;
            if (j + r < WW && srow[j + r]) hit = 1;
            if (hit) { found = 1; break; }
        }
        g = found ? (float)r : 768.0f;              // BIG = H + W
    }
    g_g2[(size_t)rowIdx * WW + j] = g * g;
}

// ---------------------------------------------------------------------------
// Kernel 2: exact vertical lower-envelope min via bounded outward search,
// fused with sigmoid, |p - t|, sqrt, and block reduction.
// Thread -> pixel linear mapping keeps consecutive j in consecutive lanes,
// so the column-strided g2 reads are fully coalesced per warp per r.
// Early exit is exact: if r*r >= best, no row at offset >= r can improve.
// ---------------------------------------------------------------------------
__global__ void loss_kernel(const float* __restrict__ logits,
                            const int* __restrict__ targets) {
    const int idx = blockIdx.x * blockDim.x + threadIdx.x;   // < NPIX
    const int j = idx % WW;
    const int i = (idx / WW) % HH;
    const int b = idx / (WW * HH);

    const float* g2img = g_g2 + (size_t)b * HH * WW;

    float best = g2img[i * WW + j];
    #pragma unroll 1
    for (int r = 1; r < HH; ++r) {
        const float r2 = (float)(r * r);
        if (r2 >= best) break;
        if (i - r >= 0) best = fminf(best, r2 + g2img[(i - r) * WW + j]);
        if (i + r < HH) best = fminf(best, r2 + g2img[(i + r) * WW + j]);
    }
    const float dist = sqrtf(best);

    const float x = logits[idx];
    const float p = 1.0f / (1.0f + expf(-x));
    const float t = (float)targets[idx];
    float val = fabsf(p - t) * dist;

    // Warp reduction
    #pragma unroll
    for (int off = 16; off > 0; off >>= 1)
        val += __shfl_xor_sync(0xFFFFFFFFu, val, off);

    __shared__ float warp_sums[8];                  // 256 threads = 8 warps
    const int lane = threadIdx.x & 31;
    const int wid = threadIdx.x >> 5;
    if (lane == 0) warp_sums[wid] = val;
    __syncthreads();
    if (wid == 0) {
        float s = (lane < (blockDim.x >> 5)) ? warp_sums[lane] : 0.0f;
        #pragma unroll
        for (int off = 4; off > 0; off >>= 1)
            s += __shfl_xor_sync(0xFFFFFFFFu, s, off);
        if (lane == 0) atomicAdd(&g_accum, s);
    }
}

// ---------------------------------------------------------------------------
// Kernel 3: finalize — mean over all pixels (== mean of per-sample means,
// since all samples have identical size).
// ---------------------------------------------------------------------------
__global__ void finalize_kernel(float* __restrict__ out) {
    out[0] = g_accum * (1.0f / (float)NPIX);
}

extern "C" void kernel_launch(void* const* d_in, const int* in_sizes, int n_in,
                              void* d_out, int out_size) {
    const float* logits = (const float*)d_in[0];
    const int* targets = (const int*)d_in[1];
    float* out = (float*)d_out;

    (void)in_sizes; (void)n_in; (void)out_size;

    // 1) Horizontal squared distances (+ accumulator zeroing)
    row_dist_kernel<<<BB * HH, WW>>>(targets);

    // 2) Vertical envelope + loss + reduction
    const int threads = 256;
    const int blocks = NPIX / threads;              // 9216
    loss_kernel<<<blocks, threads>>>(logits, targets);

    // 3) Final mean
    finalize_kernel<<<1, 1>>>(out);
}

// round 2
// speedup vs baseline: 1.8520x; 1.8520x over previous
#include <cuda_runtime.h>
#include <math.h>

#define BB 16
#define HH 384
#define WW 384
#define NPIX (BB * HH * WW)
#define NWORDS 12               // 384 / 32
#define ROWS_PER_BLOCK 4

// Scratch: squared horizontal distance per pixel (16B-aligned for float4 loads)
__device__ __align__(16) float g_g2[NPIX];

// ---------------------------------------------------------------------------
// Kernel 1: per-row 1D distance to nearest foreground pixel (exact), via
// warp-ballot bitmasks + clz/ffs nearest-set-bit. 384 threads = 12 warps per
// row; 4 rows per block. Common case (nearest fg within own 32-bit word) is
// branch-light; word-scan fallback is exact. No-fg row -> g = BIG = 768
// (matches reference clip). Also zeroes out[0].
// ---------------------------------------------------------------------------
__global__ void row_dist_kernel(const int* __restrict__ targets,
                                float* __restrict__ out) {
    __shared__ unsigned smask[ROWS_PER_BLOCK][NWORDS];
    const int j = threadIdx.x;                      // 0..383
    const int row0 = blockIdx.x * ROWS_PER_BLOCK;   // 0..6143 step 4
    const int wj = j >> 5;
    const int bj = j & 31;

    if (blockIdx.x == 0 && j == 0) out[0] = 0.0f;

    // Build fg bitmasks for 4 rows
    #pragma unroll
    for (int k = 0; k < ROWS_PER_BLOCK; ++k) {
        const int fg = targets[(size_t)(row0 + k) * WW + j] != 0;
        const unsigned m = __ballot_sync(0xFFFFFFFFu, fg);
        if (bj == 0) smask[k][wj] = m;
    }
    __syncthreads();

    #pragma unroll
    for (int k = 0; k < ROWS_PER_BLOCK; ++k) {
        const unsigned* mask = smask[k];
        const unsigned own = mask[wj];

        // nearest set bit at position <= j
        int dl;
        const unsigned ml = own & (0xFFFFFFFFu >> (31 - bj));
        if (ml) {
            dl = bj - (31 - __clz(ml));
        } else {
            dl = 0x7FFFFF;
            for (int w = wj - 1; w >= 0; --w) {
                const unsigned m = mask[w];
                if (m) { dl = j - (w * 32 + 31 - __clz(m)); break; }
            }
        }

        // nearest set bit at position >= j
        int dr;
        const unsigned mr = own & (0xFFFFFFFFu << bj);
        if (mr) {
            dr = (__ffs(mr) - 1) - bj;
        } else {
            dr = 0x7FFFFF;
            for (int w = wj + 1; w < NWORDS; ++w) {
                const unsigned m = mask[w];
                if (m) { dr = (w * 32 + __ffs(m) - 1) - j; break; }
            }
        }

        const int d = min(dl, dr);
        const float g = (d > 768) ? 768.0f : (float)d;   // BIG = H + W
        g_g2[(size_t)(row0 + k) * WW + j] = g * g;
    }
}

// ---------------------------------------------------------------------------
// Kernel 2: exact vertical lower-envelope min (bounded outward search) fused
// with sigmoid, |p-t|, sqrt, block reduction, and final scaled atomicAdd.
// 4 consecutive columns per thread: every search iteration is ONE float4 load
// of g2[(i +- r)][j..j+3] serving 4 pixels. Early exit when r^2 >= max(best)
// is exact for all 4 lanes' pixels.
// ---------------------------------------------------------------------------
__global__ void loss_kernel(const float* __restrict__ logits,
                            const int* __restrict__ targets,
                            float* __restrict__ out) {
    const int tid = blockIdx.x * blockDim.x + threadIdx.x;   // < NPIX/4
    const int base = tid * 4;
    const int j = base % WW;                  // multiple of 4 -> 16B aligned
    const int i = (base / WW) % HH;
    const int b = base / (WW * HH);

    const float* g2img = g_g2 + (size_t)b * HH * WW;

    float4 b4 = *(const float4*)(g2img + i * WW + j);
    float best0 = b4.x, best1 = b4.y, best2 = b4.z, best3 = b4.w;
    float bmax = fmaxf(fmaxf(best0, best1), fmaxf(best2, best3));

    #pragma unroll 1
    for (int r = 1; r < HH; ++r) {
        const float r2 = (float)(r * r);
        if (r2 >= bmax) break;
        if (i - r >= 0) {
            const float4 u = *(const float4*)(g2img + (i - r) * WW + j);
            best0 = fminf(best0, r2 + u.x);
            best1 = fminf(best1, r2 + u.y);
            best2 = fminf(best2, r2 + u.z);
            best3 = fminf(best3, r2 + u.w);
        }
        if (i + r < HH) {
            const float4 v = *(const float4*)(g2img + (i + r) * WW + j);
            best0 = fminf(best0, r2 + v.x);
            best1 = fminf(best1, r2 + v.y);
            best2 = fminf(best2, r2 + v.z);
            best3 = fminf(best3, r2 + v.w);
        }
        bmax = fmaxf(fmaxf(best0, best1), fmaxf(best2, best3));
    }

    const float4 lg = *(const float4*)(logits + base);
    const int4  tg = *(const int4*)(targets + base);

    float val;
    {
        const float p0 = 1.0f / (1.0f + __expf(-lg.x));
        const float p1 = 1.0f / (1.0f + __expf(-lg.y));
        const float p2 = 1.0f / (1.0f + __expf(-lg.z));
        const float p3 = 1.0f / (1.0f + __expf(-lg.w));
        val  = fabsf(p0 - (float)tg.x) * sqrtf(best0);
        val += fabsf(p1 - (float)tg.y) * sqrtf(best1);
        val += fabsf(p2 - (float)tg.z) * sqrtf(best2);
        val += fabsf(p3 - (float)tg.w) * sqrtf(best3);
    }

    // Warp reduction
    #pragma unroll
    for (int off = 16; off > 0; off >>= 1)
        val += __shfl_xor_sync(0xFFFFFFFFu, val, off);

    __shared__ float warp_sums[8];                  // 256 threads = 8 warps
    const int lane = threadIdx.x & 31;
    const int wid = threadIdx.x >> 5;
    if (lane == 0) warp_sums[wid] = val;
    __syncthreads();
    if (wid == 0) {
        float s = (lane < (blockDim.x >> 5)) ? warp_sums[lane] : 0.0f;
        #pragma unroll
        for (int off = 4; off > 0; off >>= 1)
            s += __shfl_xor_sync(0xFFFFFFFFu, s, off);
        if (lane == 0) atomicAdd(out, s * (1.0f / (float)NPIX));
    }
}

extern "C" void kernel_launch(void* const* d_in, const int* in_sizes, int n_in,
                              void* d_out, int out_size) {
    const float* logits = (const float*)d_in[0];
    const int* targets = (const int*)d_in[1];
    float* out = (float*)d_out;

    (void)in_sizes; (void)n_in; (void)out_size;

    // 1) Horizontal squared distances (bitmask-based) + out zeroing
    row_dist_kernel<<<(BB * HH) / ROWS_PER_BLOCK, WW>>>(targets, out);

    // 2) Vertical envelope + loss + reduction + scaled atomic accumulate
    const int threads = 256;
    const int blocks = (NPIX / 4) / threads;        // 2304
    loss_kernel<<<blocks, threads>>>(logits, targets, out);
}